// round 4
// baseline (speedup 1.0000x reference)
#include <cuda_runtime.h>
#include <cstdint>

// SpikeFP64ExtractLow6 — warp-ballot + streaming cache hints + low-reg ballot.
// Per row of 64 {0,1} floats:
//   e = int from x[1..11] (x[1] MSB), s = (e + 1025) & 2047
//   M = 0b1 m0..m5 with m_i = x[12+i]
//   v = (s <= 5) ? (M >> (6 - s)) & 63 : 0
//   out[row][j] = bit (5-j) of v, as float.

__device__ __forceinline__ unsigned decode_v(unsigned rowmask) {
    unsigned rb = __brev(rowmask);
    unsigned e  = (rb >> 20) & 0x7FFu;         // x[1]=MSB ... x[11]=LSB
    unsigned s  = (e + 1025u) & 2047u;         // e - 1023 mod 2048
    unsigned M  = 64u | ((rb >> 14) & 63u);    // 1 m0 m1 m2 m3 m4 m5
    return (s <= 5u) ? ((M >> (6u - s)) & 63u) : 0u;
}

__global__ __launch_bounds__(256) void spike_extract_kernel(
        const float* __restrict__ x,
        float* __restrict__ out,
        int n) {
    const int warpId = (blockIdx.x * blockDim.x + threadIdx.x) >> 5;
    const int lane   = threadIdx.x & 31;
    const int row0   = warpId * 32;
    if (row0 >= n) return;                      // whole-warp exit only

    if (row0 + 32 <= n) {
        // ---- fast path: 32 full rows per warp ----
        const float* base = x + (size_t)row0 * 64 + lane;

        unsigned myb = 0;
        // 4 groups of 8 rows: keeps only 8 load results live -> fewer regs,
        // higher occupancy, while still batching 8 LDGs per group for MLP.
        #pragma unroll 1
        for (int g = 0; g < 4; g++) {
            float vals[8];
            #pragma unroll
            for (int i = 0; i < 8; i++)
                vals[i] = (lane < 24)
                        ? __ldcs(base + (size_t)(g * 8 + i) * 64)  // evict-first
                        : 0.0f;
            #pragma unroll
            for (int i = 0; i < 8; i++) {
                unsigned b = __ballot_sync(0xFFFFFFFFu, vals[i] != 0.0f);
                if (lane == g * 8 + i) myb = b;
            }
        }

        const unsigned v = decode_v(myb);       // lane l holds v for row row0+l

        // ---- coalesced streaming store: 192 floats = 48 float4 ----
        float4* obase = reinterpret_cast<float4*>(out + (size_t)row0 * 6);

        // round A: float4 index = lane (floats 0..127)
        {
            float4 o;
            #pragma unroll
            for (int j = 0; j < 4; j++) {
                int f  = lane * 4 + j;          // 0..127
                int sr = f / 6;                 // source row lane 0..21
                int bp = 5 - (f - sr * 6);
                unsigned vv = __shfl_sync(0xFFFFFFFFu, v, sr);
                (&o.x)[j] = (float)((vv >> bp) & 1u);
            }
            __stcs(obase + lane, o);
        }
        // round B: float4 index = 32 + lane, lanes 0..15 (floats 128..191)
        {
            float4 o;
            #pragma unroll
            for (int j = 0; j < 4; j++) {
                int f  = 128 + lane * 4 + j;
                int sr = f / 6;
                int bp = 5 - (f - sr * 6);
                int src = sr < 32 ? sr : 31;    // clamp; high lanes' data unused
                unsigned vv = __shfl_sync(0xFFFFFFFFu, v, src);
                (&o.x)[j] = (float)((vv >> bp) & 1u);
            }
            if (lane < 16) __stcs(obase + 32 + lane, o);
        }
    } else {
        // ---- tail path: scalar per-lane (never hit for n = 2e6) ----
        int row = row0 + lane;
        if (row < n) {
            const float* f = x + (size_t)row * 64;
            unsigned mask = 0;
            #pragma unroll
            for (int k = 1; k <= 17; k++)
                mask |= (f[k] != 0.0f ? 1u : 0u) << k;
            unsigned v = decode_v(mask);
            float* o = out + (size_t)row * 6;
            #pragma unroll
            for (int j = 0; j < 6; j++)
                o[j] = (float)((v >> (5 - j)) & 1u);
        }
    }
}

extern "C" void kernel_launch(void* const* d_in, const int* in_sizes, int n_in,
                              void* d_out, int out_size) {
    const float* x = (const float*)d_in[0];
    float* out = (float*)d_out;
    int n = in_sizes[0] / 64;                 // 2,000,000 rows
    int nwarps = (n + 31) / 32;
    int nthreads = nwarps * 32;
    int grid = (nthreads + 255) / 256;
    spike_extract_kernel<<<grid, 256>>>(x, out, n);
}

// round 5
// speedup vs baseline: 1.0825x; 1.0825x over previous
#include <cuda_runtime.h>
#include <cstdint>

// SpikeFP64ExtractLow6 — warp-ballot, 64 rows/warp, first-64B-granule reads.
//   e = int from x[1..11] (x[1] MSB), s = (e + 1025) & 2047
//   v = (s<=5) ? ((0b1 m0..m5) >> (6-s)) & 63 : 0,  m_i = x[12+i]
// Algebraic facts exploited:
//   * m5 = x[17] is NEVER used (always shifted out for s<=5).
//   * m4 = x[16] is used ONLY when s == 5 (prob ~1/2048) -> rare predicated load.
//   * everything else (x[1..15]) lives in bytes 4..63 = first 64B DRAM granule.
// So the bulk read footprint is 64B/row instead of 128B -> ~40% less traffic.

__device__ __forceinline__ unsigned decode_v16(unsigned mask16,
                                               const float* __restrict__ xrow) {
    unsigned rb = __brev(mask16);              // bit (31-k) = x[k]
    unsigned e  = (rb >> 20) & 0x7FFu;         // x[1]=MSB ... x[11]=LSB
    unsigned s  = (e + 1025u) & 2047u;         // e - 1023 mod 2048
    if (s > 5u) return 0u;
    unsigned Mp = 16u | ((rb >> 16) & 15u);    // 1 m0 m1 m2 m3
    if (s < 5u) return Mp >> (4u - s);         // <= 31, no mask needed
    unsigned m4 = (xrow[16] != 0.0f) ? 1u : 0u;   // rare: second granule
    return ((Mp << 1) | m4) & 63u;
}

__global__ __launch_bounds__(256) void spike_extract_kernel(
        const float* __restrict__ x,
        float* __restrict__ out,
        int n) {
    const int warpId = (blockIdx.x * blockDim.x + threadIdx.x) >> 5;
    const int lane   = threadIdx.x & 31;
    const int row0   = warpId * 64;
    if (row0 >= n) return;                      // whole-warp exit only

    if (row0 + 64 <= n) {
        // ---- fast path: 64 rows per warp ----
        // lanes 0-15: col=lane of rows row0+i; lanes 16-31: col=lane-16 of rows row0+32+i
        const float* base = x + (size_t)(row0 + ((lane >= 16) ? 32 : 0)) * 64
                              + (lane & 15);
        float vals[32];
        #pragma unroll
        for (int i = 0; i < 32; i++)            // flat batch: MLP = 32
            vals[i] = base[(size_t)i * 64];

        unsigned lo = 0, hi = 0;
        #pragma unroll
        for (int i = 0; i < 32; i++) {
            unsigned b = __ballot_sync(0xFFFFFFFFu, vals[i] != 0.0f);
            if (lane == i) { lo = b & 0xFFFFu; hi = b >> 16; }
        }

        // lane l owns rows row0+l (lo) and row0+32+l (hi)
        unsigned v_lo = decode_v16(lo, x + (size_t)(row0 + lane) * 64);
        unsigned v_hi = decode_v16(hi, x + (size_t)(row0 + 32 + lane) * 64);
        unsigned packed = v_lo | (v_hi << 8);

        // ---- coalesced store: 64 rows * 6 floats = 96 float4 ----
        float4* obase = reinterpret_cast<float4*>(out + (size_t)row0 * 6);
        #pragma unroll
        for (int k = 0; k < 3; k++) {
            float4 o;
            #pragma unroll
            for (int j = 0; j < 4; j++) {
                int f  = (k * 32 + lane) * 4 + j;   // 0..383
                int sr = f / 6;                     // source row 0..63
                int bp = 5 - (f - sr * 6);
                unsigned p  = __shfl_sync(0xFFFFFFFFu, packed, sr & 31);
                unsigned vv = (sr < 32) ? p : (p >> 8);
                (&o.x)[j] = (float)((vv >> bp) & 1u);
            }
            obase[k * 32 + lane] = o;
        }
    } else {
        // ---- tail path: scalar, lane handles rows row0+lane, row0+32+lane ----
        for (int r = row0 + lane; r < n; r += 32) {
            const float* fr = x + (size_t)r * 64;
            unsigned mask = 0;
            #pragma unroll
            for (int k = 1; k <= 15; k++)
                mask |= (fr[k] != 0.0f ? 1u : 0u) << k;
            unsigned v = decode_v16(mask, fr);
            float* o = out + (size_t)r * 6;
            #pragma unroll
            for (int j = 0; j < 6; j++)
                o[j] = (float)((v >> (5 - j)) & 1u);
        }
    }
}

extern "C" void kernel_launch(void* const* d_in, const int* in_sizes, int n_in,
                              void* d_out, int out_size) {
    const float* x = (const float*)d_in[0];
    float* out = (float*)d_out;
    int n = in_sizes[0] / 64;                 // 2,000,000 rows
    int nwarps = (n + 63) / 64;
    long long nthreads = (long long)nwarps * 32;
    int grid = (int)((nthreads + 255) / 256);
    spike_extract_kernel<<<grid, 256>>>(x, out, n);
}

// round 8
// speedup vs baseline: 1.0839x; 1.0013x over previous
#include <cuda_runtime.h>
#include <cstdint>

// SpikeFP64ExtractLow6 — warp-ballot, 64 rows/warp, rare-path m4.
//   e = int from x[1..11] (x[1] MSB), s = (e + 1025) & 2047
//   v = (s<=5) ? ((0b1 m0..m5) >> (6-s)) & 63 : 0,  m_i = x[12+i]
// m5 never used; m4 = x[16] needed only when s == 5 (p ~ 1/2048) -> loaded in a
// warp-uniform ballot-guarded rare path (issues in ~3% of warps only).
// Bulk reads: lanes 0-15 cover cols 0-15 (bytes 0-63) of each row; DRAM moves
// the full 128B line regardless (measured R1/R3/R5), so traffic is at its
// 304 MB floor. Goal of this round: keep the stream clean of stray accesses.

__global__ __launch_bounds__(256) void spike_extract_kernel(
        const float* __restrict__ x,
        float* __restrict__ out,
        int n) {
    const int warpId = (blockIdx.x * blockDim.x + threadIdx.x) >> 5;
    const int lane   = threadIdx.x & 31;
    const int row0   = warpId * 64;
    if (row0 >= n) return;                      // whole-warp exit only

    if (row0 + 64 <= n) {
        // ---- bulk load: 32 LDG in flight, L1-bypass ----
        const float* base = x + (size_t)(row0 + ((lane >= 16) ? 32 : 0)) * 64
                              + (lane & 15);
        float vals[32];
        #pragma unroll
        for (int i = 0; i < 32; i++)
            vals[i] = __ldcg(base + (size_t)i * 64);

        unsigned lo = 0, hi = 0;
        #pragma unroll
        for (int i = 0; i < 32; i++) {
            unsigned b = __ballot_sync(0xFFFFFFFFu, vals[i] != 0.0f);
            if (lane == i) { lo = b & 0xFFFFu; hi = b >> 16; }
        }

        // ---- decode: lane l owns rows row0+l (lo) and row0+32+l (hi) ----
        unsigned rb_lo = __brev(lo), rb_hi = __brev(hi);
        unsigned s_lo  = (((rb_lo >> 20) & 0x7FFu) + 1025u) & 2047u;
        unsigned s_hi  = (((rb_hi >> 20) & 0x7FFu) + 1025u) & 2047u;
        unsigned Mp_lo = 16u | ((rb_lo >> 16) & 15u);   // 1 m0 m1 m2 m3
        unsigned Mp_hi = 16u | ((rb_hi >> 16) & 15u);
        unsigned v_lo  = (s_lo <= 4u) ? (Mp_lo >> ((4u - s_lo) & 31u)) : 0u;
        unsigned v_hi  = (s_hi <= 4u) ? (Mp_hi >> ((4u - s_hi) & 31u)) : 0u;

        // rare s==5 fix-up: warp-uniform branch, load issues in ~3% of warps
        unsigned need = ((s_lo == 5u) ? 1u : 0u) | ((s_hi == 5u) ? 2u : 0u);
        if (__ballot_sync(0xFFFFFFFFu, need)) {
            if (need & 1u) {
                unsigned m4 = (x[(size_t)(row0 + lane) * 64 + 16] != 0.0f);
                v_lo = ((Mp_lo << 1) | m4) & 63u;
            }
            if (need & 2u) {
                unsigned m4 = (x[(size_t)(row0 + 32 + lane) * 64 + 16] != 0.0f);
                v_hi = ((Mp_hi << 1) | m4) & 63u;
            }
        }
        const unsigned packed = v_lo | (v_hi << 8);

        // ---- coalesced store: 64 rows * 6 floats = 96 float4 ----
        float4* obase = reinterpret_cast<float4*>(out + (size_t)row0 * 6);
        #pragma unroll
        for (int k = 0; k < 3; k++) {
            float4 o;
            #pragma unroll
            for (int j = 0; j < 4; j++) {
                int f  = (k * 32 + lane) * 4 + j;   // 0..383
                int sr = f / 6;                     // source row 0..63
                int bp = 5 - (f - sr * 6);
                unsigned p  = __shfl_sync(0xFFFFFFFFu, packed, sr & 31);
                unsigned vv = (sr < 32) ? p : (p >> 8);
                (&o.x)[j] = (float)((vv >> bp) & 1u);
            }
            obase[k * 32 + lane] = o;
        }
    } else {
        // ---- tail path (n % 64 rows; never hit for n = 2e6) ----
        for (int r = row0 + lane; r < n; r += 32) {
            const float* fr = x + (size_t)r * 64;
            unsigned e = 0;
            #pragma unroll
            for (int k = 1; k <= 11; k++)
                e = (e << 1) | (fr[k] != 0.0f ? 1u : 0u);
            unsigned s = (e + 1025u) & 2047u;
            unsigned M = 1u;
            #pragma unroll
            for (int i = 0; i < 6; i++)
                M = (M << 1) | (fr[12 + i] != 0.0f ? 1u : 0u);
            unsigned v = (s <= 5u) ? ((M >> ((6u - s) & 31u)) & 63u) : 0u;
            float* o = out + (size_t)r * 6;
            #pragma unroll
            for (int j = 0; j < 6; j++)
                o[j] = (float)((v >> (5 - j)) & 1u);
        }
    }
}

extern "C" void kernel_launch(void* const* d_in, const int* in_sizes, int n_in,
                              void* d_out, int out_size) {
    const float* x = (const float*)d_in[0];
    float* out = (float*)d_out;
    int n = in_sizes[0] / 64;                 // 2,000,000 rows
    int nwarps = (n + 63) / 64;
    long long nthreads = (long long)nwarps * 32;
    int grid = (int)((nthreads + 255) / 256);
    spike_extract_kernel<<<grid, 256>>>(x, out, n);
}

// round 9
// speedup vs baseline: 1.0916x; 1.0071x over previous
#include <cuda_runtime.h>
#include <cstdint>

// SpikeFP64ExtractLow6 — warp-ballot, 32 rows/warp, high-occupancy variant.
//   e = int from x[1..11] (x[1] MSB), s = (e + 1025) & 2047
//   v = (s<=5) ? ((0b1 m0..m5) >> (6-s)) & 63 : 0,  m_i = x[12+i]
// m5 never used; m4 = x[16] only when s == 5 (p~1/2048) -> rare ballot-guarded
// load. Bulk reads touch bytes 0..63/row (DRAM moves the 128B line anyway:
// traffic floor ~304 MB, measured across R1/R3/R5/R6).
// This round: 16 LDG/warp (lanes 0-15 = row i, lanes 16-31 = row i+16) keeps
// live regs ~16 -> ~8 blocks/SM -> chip-wide outstanding bytes up ~60%.

__global__ __launch_bounds__(256) void spike_extract_kernel(
        const float* __restrict__ x,
        float* __restrict__ out,
        int n) {
    const int warpId = (blockIdx.x * blockDim.x + threadIdx.x) >> 5;
    const int lane   = threadIdx.x & 31;
    const int row0   = warpId * 32;
    if (row0 >= n) return;                      // whole-warp exit only

    if (row0 + 32 <= n) {
        // ---- bulk load: 16 LDG in flight per warp ----
        // lanes 0-15: col=lane of row row0+i; lanes 16-31: col=lane-16 of row row0+16+i
        const float* base = x + (size_t)(row0 + ((lane >= 16) ? 16 : 0)) * 64
                              + (lane & 15);
        float vals[16];
        #pragma unroll
        for (int i = 0; i < 16; i++)
            vals[i] = __ldcg(base + (size_t)i * 64);

        unsigned myb = 0;
        #pragma unroll
        for (int i = 0; i < 16; i++) {
            unsigned b = __ballot_sync(0xFFFFFFFFu, vals[i] != 0.0f);
            if ((lane & 15) == i)
                myb = (lane < 16) ? (b & 0xFFFFu) : (b >> 16);
        }
        // lane l owns row row0 + ((l<16) ? l : l) ... mapping:
        //   lanes 0-15 own rows row0+lane (from lo halves)
        //   lanes 16-31 own rows row0+lane (= row0+16+(lane-16), from hi halves)
        // i.e. lane l owns row row0 + l.  (lo: i=l; hi: i=l-16 -> row 16+i = l)

        // ---- decode ----
        unsigned rb = __brev(myb);
        unsigned s  = (((rb >> 20) & 0x7FFu) + 1025u) & 2047u;
        unsigned Mp = 16u | ((rb >> 16) & 15u);          // 1 m0 m1 m2 m3
        unsigned v  = (s <= 4u) ? (Mp >> ((4u - s) & 31u)) : 0u;

        // rare s==5 fix-up: warp-uniform branch
        if (__ballot_sync(0xFFFFFFFFu, s == 5u)) {
            if (s == 5u) {
                unsigned m4 = (x[(size_t)(row0 + lane) * 64 + 16] != 0.0f);
                v = ((Mp << 1) | m4) & 63u;
            }
        }

        // ---- coalesced store: 32 rows * 6 floats = 48 float4 ----
        float4* obase = reinterpret_cast<float4*>(out + (size_t)row0 * 6);
        // round A: float4 index = lane (floats 0..127)
        {
            float4 o;
            #pragma unroll
            for (int j = 0; j < 4; j++) {
                int f  = lane * 4 + j;              // 0..127
                int sr = f / 6;                     // source row 0..21
                int bp = 5 - (f - sr * 6);
                unsigned vv = __shfl_sync(0xFFFFFFFFu, v, sr);
                (&o.x)[j] = (float)((vv >> bp) & 1u);
            }
            obase[lane] = o;
        }
        // round B: float4 index = 32 + lane, lanes 0..15 (floats 128..191)
        {
            float4 o;
            #pragma unroll
            for (int j = 0; j < 4; j++) {
                int f  = 128 + lane * 4 + j;
                int sr = f / 6;
                int bp = 5 - (f - sr * 6);
                int src = sr < 32 ? sr : 31;        // clamp; high lanes unused
                unsigned vv = __shfl_sync(0xFFFFFFFFu, v, src);
                (&o.x)[j] = (float)((vv >> bp) & 1u);
            }
            if (lane < 16) obase[32 + lane] = o;
        }
    } else {
        // ---- tail path (n % 32 rows; never hit for n = 2e6) ----
        int r = row0 + lane;
        if (r < n) {
            const float* fr = x + (size_t)r * 64;
            unsigned e = 0;
            #pragma unroll
            for (int k = 1; k <= 11; k++)
                e = (e << 1) | (fr[k] != 0.0f ? 1u : 0u);
            unsigned s = (e + 1025u) & 2047u;
            unsigned M = 1u;
            #pragma unroll
            for (int i = 0; i < 6; i++)
                M = (M << 1) | (fr[12 + i] != 0.0f ? 1u : 0u);
            unsigned v = (s <= 5u) ? ((M >> ((6u - s) & 31u)) & 63u) : 0u;
            float* o = out + (size_t)r * 6;
            #pragma unroll
            for (int j = 0; j < 6; j++)
                o[j] = (float)((v >> (5 - j)) & 1u);
        }
    }
}

extern "C" void kernel_launch(void* const* d_in, const int* in_sizes, int n_in,
                              void* d_out, int out_size) {
    const float* x = (const float*)d_in[0];
    float* out = (float*)d_out;
    int n = in_sizes[0] / 64;                 // 2,000,000 rows
    int nwarps = (n + 31) / 32;
    long long nthreads = (long long)nwarps * 32;
    int grid = (int)((nthreads + 255) / 256);
    spike_extract_kernel<<<grid, 256>>>(x, out, n);
}